// round 12
// baseline (speedup 1.0000x reference)
#include <cuda_runtime.h>
#include <cuda_fp16.h>
#include <math.h>
#include <stdint.h>

// ================= scratch (device globals; no allocation allowed) =========
__device__ float  g_h [16 * 64 * 64 * 64];            // conv1 output, NCHW (fp32)
__device__ float  g_bc[16 * 96 * 64 * 64];            // conv2 output, NCHW (fp32)
__device__ __half g_Ah[(size_t)65536 * 1024];         // bases_out (half), p=(n*64+w)*64+h, d=c*16+f
__device__ __half g_Bh[128 * 1024];                   // coef as half [o][k]
__device__ __half g_W1h[9 * 64 * 64];                 // conv1 w fp16 [k][oc][ic]
__device__ __half g_W2h[9 * 96 * 64];                 // conv2 w fp16 [k][oc][ic]
__device__ float  g_a1[64], g_b1[64], g_a2[96], g_b2[96];

__device__ __forceinline__ uint32_t smem_u32(const void* p) {
    uint32_t a;
    asm("{ .reg .u64 t; cvta.to.shared.u64 t, %1; cvt.u32.u64 %0, t; }" : "=r"(a) : "l"(p));
    return a;
}

#define CP_ASYNC16(dst, src) \
    asm volatile("cp.async.ca.shared.global [%0], [%1], 16;" :: "r"(dst), "l"(src))
#define CP_ASYNC_COMMIT() asm volatile("cp.async.commit_group;" ::: "memory")
#define CP_ASYNC_WAIT(n)  asm volatile("cp.async.wait_group %0;" :: "n"(n) : "memory")

#define LDMATRIX_X4(r0, r1, r2, r3, addr) \
    asm volatile("ldmatrix.sync.aligned.m8n8.x4.shared.b16 {%0,%1,%2,%3}, [%4];" \
                 : "=r"(r0), "=r"(r1), "=r"(r2), "=r"(r3) : "r"(addr))

#define MMA16816(d, a, b) \
    asm volatile("mma.sync.aligned.m16n8k16.row.col.f32.f16.f16.f32 " \
                 "{%0,%1,%2,%3}, {%4,%5,%6,%7}, {%8,%9}, {%0,%1,%2,%3};" \
                 : "+f"((d)[0]), "+f"((d)[1]), "+f"((d)[2]), "+f"((d)[3]) \
                 : "r"((a)[0]), "r"((a)[1]), "r"((a)[2]), "r"((a)[3]), \
                   "r"((b)[0]), "r"((b)[1]))

// ================= precompute kernels ======================================
__global__ void prep_affine(const float* __restrict__ b1, const float* __restrict__ g1,
                            const float* __restrict__ be1, const float* __restrict__ m1,
                            const float* __restrict__ v1,
                            const float* __restrict__ b2, const float* __restrict__ g2,
                            const float* __restrict__ be2, const float* __restrict__ m2,
                            const float* __restrict__ v2)
{
    int i = threadIdx.x;
    if (i < 64) {
        float a = g1[i] * rsqrtf(v1[i] + 1e-5f);
        g_a1[i] = a;
        g_b1[i] = (b1[i] - m1[i]) * a + be1[i];
    }
    if (i < 96) {
        float a = g2[i] * rsqrtf(v2[i] + 1e-5f);
        g_a2[i] = a;
        g_b2[i] = (b2[i] - m2[i]) * a + be2[i];
    }
}

__global__ void cvt_coef_kernel(const float* __restrict__ c)
{
    int i = blockIdx.x * 256 + threadIdx.x;   // 512 x 256 = 131072
    g_Bh[i] = __float2half(c[i]);
}

// conv weights OIHW fp32 -> [k][oc][ic] fp16
__global__ void cvt_w_kernel(const float* __restrict__ w1, const float* __restrict__ w2)
{
    int i = blockIdx.x * 256 + threadIdx.x;   // 216 x 256 >= 55296
    if (i < 64 * 64 * 9) {
        int oc = i / 576, rem = i % 576, ic = rem / 9, k = rem % 9;
        g_W1h[(k * 64 + oc) * 64 + ic] = __float2half(w1[i]);
    }
    if (i < 96 * 64 * 9) {
        int oc = i / 576, rem = i % 576, ic = rem / 9, k = rem % 9;
        g_W2h[(k * 96 + oc) * 64 + ic] = __float2half(w2[i]);
    }
}

// ================= HMMA implicit-GEMM conv3x3 + BN + tanh ==================
template <int OC>
__global__ __launch_bounds__(256)
void conv_hmma_kernel(const float* __restrict__ xin, const __half* __restrict__ Wh,
                      const float* __restrict__ aff_a, const float* __restrict__ aff_b,
                      float* __restrict__ out)
{
    constexpr int NPW = OC / 2;          // oc per warp_n
    constexpr int NPJ = NPW / 16;        // B ldmatrix.x4 loads per warp
    constexpr int NNI = NPW / 8;         // n8 fragments per warp
    constexpr int XS_HALFS = 4 * 66 * 72;

    extern __shared__ __align__(16) char conv_sm[];
    __half* xs = (__half*)conv_sm;                    // [4][66][72]
    __half* Bs = (__half*)conv_sm + XS_HALFS;         // [2][OC][72]

    const int tid  = threadIdx.x;
    const int wid  = tid >> 5;
    const int lane = tid & 31;
    const int warp_m = wid & 3;
    const int warp_n = wid >> 2;
    const int h0 = blockIdx.x * 2;
    const int n  = blockIdx.y;

    auto wload = [&](int k, int buf) {
#pragma unroll
        for (int i = tid; i < OC * 8; i += 256) {
            int oc = i >> 3, c = i & 7;
            uint32_t dst = smem_u32(&Bs[(buf * OC + oc) * 72 + c * 8]);
            CP_ASYNC16(dst, Wh + ((size_t)k * OC + oc) * 64 + c * 8);
        }
        CP_ASYNC_COMMIT();
    };
    wload(0, 0);

    // fill xs (zero-padded halo), coalesced over w
    for (int idx = tid; idx < 4 * 64 * 66; idx += 256) {
        int w66 = idx % 66;
        int rest = idx / 66;
        int ic = rest & 63;
        int h4 = rest >> 6;
        int h = h0 - 1 + h4, w = w66 - 1;
        float v = 0.f;
        if (h >= 0 && h < 64 && w >= 0 && w < 64)
            v = xin[((n * 64 + ic) * 64 + h) * 64 + w];
        xs[(h4 * 66 + w66) * 72 + ic] = __float2half(v);
    }

    const int a_row  = lane & 15;
    const int a_colL = (lane >> 4) * 8;
    const int b_rowL = ((lane >> 4) * 8) + (lane & 7);
    const int b_colL = ((lane >> 3) & 1) * 8;

    int arow_lin[2];
#pragma unroll
    for (int mi = 0; mi < 2; mi++) {
        int m = warp_m * 32 + mi * 16 + a_row;
        arow_lin[mi] = (m >> 6) * 66 + (m & 63);
    }
    const uint32_t xbase = smem_u32(xs);

    float acc[2][NNI][4];
#pragma unroll
    for (int mi = 0; mi < 2; mi++)
#pragma unroll
        for (int ni = 0; ni < NNI; ni++)
#pragma unroll
            for (int q = 0; q < 4; q++) acc[mi][ni][q] = 0.f;

    for (int k = 0; k < 9; k++) {
        const int buf = k & 1;
        CP_ASYNC_WAIT(0);
        __syncthreads();
        if (k + 1 < 9) wload(k + 1, buf ^ 1);

        const int dh = k / 3, dw = k % 3;
        const uint32_t shift_off = (uint32_t)((dh * 66 + dw) * 72) * 2u;
        uint32_t arow_addr[2];
#pragma unroll
        for (int mi = 0; mi < 2; mi++)
            arow_addr[mi] = xbase + (uint32_t)(arow_lin[mi] * 72) * 2u + shift_off;
        const uint32_t bbase = smem_u32(&Bs[buf * OC * 72]);

#pragma unroll
        for (int kk = 0; kk < 4; kk++) {
            uint32_t a[2][4];
#pragma unroll
            for (int mi = 0; mi < 2; mi++)
                LDMATRIX_X4(a[mi][0], a[mi][1], a[mi][2], a[mi][3],
                            arow_addr[mi] + (uint32_t)(kk * 16 + a_colL) * 2u);
            uint32_t b[NPJ][4];
#pragma unroll
            for (int pj = 0; pj < NPJ; pj++) {
                int row = warp_n * NPW + pj * 16 + b_rowL;
                LDMATRIX_X4(b[pj][0], b[pj][1], b[pj][2], b[pj][3],
                            bbase + (uint32_t)(row * 72 + kk * 16 + b_colL) * 2u);
            }
#pragma unroll
            for (int mi = 0; mi < 2; mi++) {
#pragma unroll
                for (int ni = 0; ni < NNI; ni++) {
                    uint32_t bf[2];
                    bf[0] = b[ni >> 1][(ni & 1) * 2 + 0];
                    bf[1] = b[ni >> 1][(ni & 1) * 2 + 1];
                    MMA16816(acc[mi][ni], a[mi], bf);
                }
            }
        }
        __syncthreads();
    }

    const int lr = lane >> 2;
    const int lc = (lane & 3) * 2;
#pragma unroll
    for (int mi = 0; mi < 2; mi++) {
        int mbase = warp_m * 32 + mi * 16;
#pragma unroll
        for (int ni = 0; ni < NNI; ni++) {
            int oc0 = warp_n * NPW + ni * 8 + lc;
            float a0 = __ldg(&aff_a[oc0]),     c0 = __ldg(&aff_b[oc0]);
            float a1 = __ldg(&aff_a[oc0 + 1]), c1 = __ldg(&aff_b[oc0 + 1]);
#pragma unroll
            for (int hf = 0; hf < 2; hf++) {
                int m = mbase + lr + hf * 8;
                int h = h0 + (m >> 6), w = m & 63;
                out[((n * OC + oc0)     * 64 + h) * 64 + w] = tanhf(acc[mi][ni][hf * 2 + 0] * a0 + c0);
                out[((n * OC + oc0 + 1) * 64 + h) * 64 + w] = tanhf(acc[mi][ni][hf * 2 + 1] * a1 + c1);
            }
        }
    }
}

// ================= atoms + unfold -> A (half) ==============================
// R10 structure (measured-good). ONE change: the vals inner loop reads
// atoms_s via float4 broadcasts (36 LDS.128 instead of 144 scalar LDS per
// (wi,c) pair). Same FMA order per k-step -> identical numerics.
__global__ __launch_bounds__(256)
void atoms_unfold_kernel(const float* __restrict__ x, const float* __restrict__ bc,
                         const float* __restrict__ bases)
{
    __shared__ float xs[3 * 34 * 65];                     // [(r*34+col)*65 + c]
    __shared__ __align__(16) float atoms_s[32 * 9 * 16];  // [(wi*9+k)*16 + f]
    __shared__ float bs[54];                              // bases [t][k]

    const int w0 = blockIdx.x * 32;
    const int h  = blockIdx.y;
    const int n  = blockIdx.z;
    const int tid = threadIdx.x;

    if (tid < 54) bs[tid] = bases[tid];

    for (int idx = tid; idx < 64 * 102; idx += 256) {
        int c   = idx / 102;
        int rem = idx - c * 102;
        int r   = rem / 34;
        int col = rem - r * 34;
        int gh = h + r - 1, gw = w0 + col - 1;
        float v = 0.f;
        if (gh >= 0 && gh < 64 && gw >= 0 && gw < 64)
            v = x[((n * 64 + c) * 64 + gh) * 64 + gw];
        xs[(r * 34 + col) * 65 + c] = v;
    }
    __syncthreads();

    // atoms: 512 (wi,f) pairs, 2 per thread
#pragma unroll
    for (int pr = 0; pr < 2; pr++) {
        int pair = tid + pr * 256;
        int wi = pair >> 4;
        int f  = pair & 15;
        float cv[6];
#pragma unroll
        for (int t = 0; t < 6; t++)
            cv[t] = bc[((n * 96 + f * 6 + t) * 64 + (w0 + wi)) * 64 + h];
#pragma unroll
        for (int k = 0; k < 9; k++) {
            float s = 0.f;
#pragma unroll
            for (int t = 0; t < 6; t++) s += cv[t] * bs[t * 9 + k];
            atoms_s[(wi * 9 + k) * 16 + f] = s;
        }
    }
    __syncthreads();

    // bases_out: 2048 (wi,c) pairs, 8 per thread; c fastest in warp
#pragma unroll 1
    for (int pr = 0; pr < 8; pr++) {
        int pair = tid + pr * 256;
        int c  = pair & 63;
        int wi = pair >> 6;
        float xr[9];
#pragma unroll
        for (int kh = 0; kh < 3; kh++)
#pragma unroll
            for (int kw = 0; kw < 3; kw++)
                xr[kh * 3 + kw] = xs[(kh * 34 + wi + kw) * 65 + c];

        const float4* ap = (const float4*)&atoms_s[wi * 144];  // [k][f/4] float4s
        float vals[16];
#pragma unroll
        for (int q = 0; q < 16; q++) vals[q] = 0.f;
#pragma unroll
        for (int k = 0; k < 9; k++) {
            float xk = xr[k];
            float4 q0 = ap[k * 4 + 0];
            float4 q1 = ap[k * 4 + 1];
            float4 q2 = ap[k * 4 + 2];
            float4 q3 = ap[k * 4 + 3];
            vals[0]  += xk * q0.x;  vals[1]  += xk * q0.y;
            vals[2]  += xk * q0.z;  vals[3]  += xk * q0.w;
            vals[4]  += xk * q1.x;  vals[5]  += xk * q1.y;
            vals[6]  += xk * q1.z;  vals[7]  += xk * q1.w;
            vals[8]  += xk * q2.x;  vals[9]  += xk * q2.y;
            vals[10] += xk * q2.z;  vals[11] += xk * q2.w;
            vals[12] += xk * q3.x;  vals[13] += xk * q3.y;
            vals[14] += xk * q3.z;  vals[15] += xk * q3.w;
        }

        size_t p = (size_t)((n * 64 + (w0 + wi)) * 64 + h);
        union { __half2 h2[4]; uint4 u; } pk0, pk1;
#pragma unroll
        for (int q = 0; q < 4; q++) {
            pk0.h2[q] = __floats2half2_rn(vals[2 * q],     vals[2 * q + 1]);
            pk1.h2[q] = __floats2half2_rn(vals[8 + 2 * q], vals[8 + 2 * q + 1]);
        }
        uint4* dst = (uint4*)&g_Ah[p * 1024 + c * 16];
        dst[0] = pk0.u;
        dst[1] = pk1.u;
    }
}

// ================= HMMA GEMM: out = A(65536x1024) * coef^T ================
#define SM_STRIDE 40
__global__ __launch_bounds__(256)
void gemm_hmma_kernel(const __half* __restrict__ A, const __half* __restrict__ B,
                      float* __restrict__ out)
{
    __shared__ __align__(16) __half As[2][128 * SM_STRIDE];
    __shared__ __align__(16) __half Bs[2][128 * SM_STRIDE];

    const int tid  = threadIdx.x;
    const int wid  = tid >> 5;
    const int lane = tid & 31;
    const int p0   = blockIdx.x * 128;

    const int warp_m = wid & 1;
    const int warp_n = wid >> 1;

    float acc[4][4][4];
#pragma unroll
    for (int mi = 0; mi < 4; mi++)
#pragma unroll
        for (int ni = 0; ni < 4; ni++)
#pragma unroll
            for (int q = 0; q < 4; q++) acc[mi][ni][q] = 0.f;

    const int r0 = tid >> 2, c0 = tid & 3;
    const int r1 = (tid + 256) >> 2, c1 = tid & 3;

    auto load_stage = [&](int ks, int buf) {
        const __half* ag = &A[(size_t)p0 * 1024 + ks * 32];
        uint32_t aD0 = smem_u32(&As[buf][r0 * SM_STRIDE + c0 * 8]);
        uint32_t aD1 = smem_u32(&As[buf][r1 * SM_STRIDE + c1 * 8]);
        CP_ASYNC16(aD0, ag + (size_t)r0 * 1024 + c0 * 8);
        CP_ASYNC16(aD1, ag + (size_t)r1 * 1024 + c1 * 8);
        const __half* bg = &B[ks * 32];
        uint32_t bD0 = smem_u32(&Bs[buf][r0 * SM_STRIDE + c0 * 8]);
        uint32_t bD1 = smem_u32(&Bs[buf][r1 * SM_STRIDE + c1 * 8]);
        CP_ASYNC16(bD0, bg + (size_t)r0 * 1024 + c0 * 8);
        CP_ASYNC16(bD1, bg + (size_t)r1 * 1024 + c1 * 8);
        CP_ASYNC_COMMIT();
    };

    load_stage(0, 0);

    const int a_row_l = (lane & 15);
    const int a_col_l = (lane >> 4) * 8;
    const int b_row_l = ((lane >> 4) * 8) + (lane & 7);
    const int b_col_l = ((lane >> 3) & 1) * 8;

    for (int ks = 0; ks < 32; ks++) {
        const int buf = ks & 1;
        if (ks + 1 < 32) {
            load_stage(ks + 1, buf ^ 1);
            CP_ASYNC_WAIT(1);
        } else {
            CP_ASYNC_WAIT(0);
        }
        __syncthreads();

        const uint32_t aB = smem_u32(As[buf]);
        const uint32_t bB = smem_u32(Bs[buf]);
#pragma unroll
        for (int kk = 0; kk < 2; kk++) {
            uint32_t a[4][4];
#pragma unroll
            for (int mi = 0; mi < 4; mi++) {
                int row = warp_m * 64 + mi * 16 + a_row_l;
                int col = kk * 16 + a_col_l;
                LDMATRIX_X4(a[mi][0], a[mi][1], a[mi][2], a[mi][3],
                            aB + (uint32_t)(row * SM_STRIDE + col) * 2);
            }
            uint32_t b[2][4];
#pragma unroll
            for (int pj = 0; pj < 2; pj++) {
                int row = warp_n * 32 + pj * 16 + b_row_l;
                int col = kk * 16 + b_col_l;
                LDMATRIX_X4(b[pj][0], b[pj][1], b[pj][2], b[pj][3],
                            bB + (uint32_t)(row * SM_STRIDE + col) * 2);
            }
#pragma unroll
            for (int mi = 0; mi < 4; mi++) {
#pragma unroll
                for (int ni = 0; ni < 4; ni++) {
                    uint32_t bf[2];
                    bf[0] = b[ni >> 1][(ni & 1) * 2 + 0];
                    bf[1] = b[ni >> 1][(ni & 1) * 2 + 1];
                    MMA16816(acc[mi][ni], a[mi], bf);
                }
            }
        }
        __syncthreads();
    }

    const int lr = lane >> 2;
    const int lc = (lane & 3) * 2;
#pragma unroll
    for (int mi = 0; mi < 4; mi++) {
#pragma unroll
        for (int ni = 0; ni < 4; ni++) {
            int obase = warp_n * 32 + ni * 8 + lc;
#pragma unroll
            for (int half_ = 0; half_ < 2; half_++) {
                int p = p0 + warp_m * 64 + mi * 16 + lr + half_ * 8;
                int nn = p >> 12, wq = (p >> 6) & 63, hh = p & 63;
                size_t base = (((size_t)nn * 128) * 64 + (size_t)wq) * 64 + hh;
                out[base + (size_t)obase       * 4096] = acc[mi][ni][half_ * 2 + 0];
                out[base + (size_t)(obase + 1) * 4096] = acc[mi][ni][half_ * 2 + 1];
            }
        }
    }
}

// ================= launch ===================================================
extern "C" void kernel_launch(void* const* d_in, const int* in_sizes, int n_in,
                              void* d_out, int out_size)
{
    const float* x        = (const float*)d_in[0];
    const float* conv1_w  = (const float*)d_in[1];
    const float* conv1_b  = (const float*)d_in[2];
    const float* bn1_g    = (const float*)d_in[3];
    const float* bn1_be   = (const float*)d_in[4];
    const float* bn1_m    = (const float*)d_in[5];
    const float* bn1_v    = (const float*)d_in[6];
    const float* conv2_w  = (const float*)d_in[7];
    const float* conv2_b  = (const float*)d_in[8];
    const float* bn2_g    = (const float*)d_in[9];
    const float* bn2_be   = (const float*)d_in[10];
    const float* bn2_m    = (const float*)d_in[11];
    const float* bn2_v    = (const float*)d_in[12];
    const float* bases    = (const float*)d_in[13];
    const float* coef     = (const float*)d_in[14];
    float* out = (float*)d_out;

    static float  *p_h = nullptr, *p_bc = nullptr;
    static __half *p_Ah = nullptr, *p_Bh = nullptr, *p_W1h = nullptr, *p_W2h = nullptr;
    static float  *p_a1 = nullptr, *p_b1 = nullptr, *p_a2 = nullptr, *p_b2 = nullptr;
    if (!p_h) {
        cudaGetSymbolAddress((void**)&p_h,   g_h);
        cudaGetSymbolAddress((void**)&p_bc,  g_bc);
        cudaGetSymbolAddress((void**)&p_Ah,  g_Ah);
        cudaGetSymbolAddress((void**)&p_Bh,  g_Bh);
        cudaGetSymbolAddress((void**)&p_W1h, g_W1h);
        cudaGetSymbolAddress((void**)&p_W2h, g_W2h);
        cudaGetSymbolAddress((void**)&p_a1,  g_a1);
        cudaGetSymbolAddress((void**)&p_b1,  g_b1);
        cudaGetSymbolAddress((void**)&p_a2,  g_a2);
        cudaGetSymbolAddress((void**)&p_b2,  g_b2);
        cudaFuncSetAttribute(conv_hmma_kernel<64>, cudaFuncAttributeMaxDynamicSharedMemorySize,
                             (4 * 66 * 72 + 2 * 64 * 72) * 2);
        cudaFuncSetAttribute(conv_hmma_kernel<96>, cudaFuncAttributeMaxDynamicSharedMemorySize,
                             (4 * 66 * 72 + 2 * 96 * 72) * 2);
    }

    prep_affine<<<1, 128>>>(conv1_b, bn1_g, bn1_be, bn1_m, bn1_v,
                            conv2_b, bn2_g, bn2_be, bn2_m, bn2_v);
    cvt_coef_kernel<<<512, 256>>>(coef);
    cvt_w_kernel<<<216, 256>>>(conv1_w, conv2_w);

    conv_hmma_kernel<64><<<dim3(32, 16), 256, (4 * 66 * 72 + 2 * 64 * 72) * 2>>>(
        x, p_W1h, p_a1, p_b1, p_h);
    conv_hmma_kernel<96><<<dim3(32, 16), 256, (4 * 66 * 72 + 2 * 96 * 72) * 2>>>(
        p_h, p_W2h, p_a2, p_b2, p_bc);

    atoms_unfold_kernel<<<dim3(2, 64, 16), 256>>>(x, p_bc, bases);

    gemm_hmma_kernel<<<512, 256>>>(p_Ah, p_Bh, out);
}

// round 15
// speedup vs baseline: 1.0953x; 1.0953x over previous
#include <cuda_runtime.h>
#include <cuda_fp16.h>
#include <math.h>
#include <stdint.h>

// ================= scratch (device globals; no allocation allowed) =========
__device__ float  g_h [16 * 64 * 64 * 64];            // conv1 output, NCHW (fp32)
__device__ float  g_bc[16 * 96 * 64 * 64];            // conv2 output, NCHW (fp32)
__device__ __half g_Bh[128 * 1024];                   // coef as half [o][k]
__device__ __half g_W1h[9 * 64 * 64];                 // conv1 w fp16 [k][oc][ic]
__device__ __half g_W2h[9 * 96 * 64];                 // conv2 w fp16 [k][oc][ic]
__device__ float  g_a1[64], g_b1[64], g_a2[96], g_b2[96];

__device__ __forceinline__ uint32_t smem_u32(const void* p) {
    uint32_t a;
    asm("{ .reg .u64 t; cvta.to.shared.u64 t, %1; cvt.u32.u64 %0, t; }" : "=r"(a) : "l"(p));
    return a;
}

#define CP_ASYNC16(dst, src) \
    asm volatile("cp.async.ca.shared.global [%0], [%1], 16;" :: "r"(dst), "l"(src))
#define CP_ASYNC_COMMIT() asm volatile("cp.async.commit_group;" ::: "memory")
#define CP_ASYNC_WAIT(n)  asm volatile("cp.async.wait_group %0;" :: "n"(n) : "memory")

#define LDMATRIX_X4(r0, r1, r2, r3, addr) \
    asm volatile("ldmatrix.sync.aligned.m8n8.x4.shared.b16 {%0,%1,%2,%3}, [%4];" \
                 : "=r"(r0), "=r"(r1), "=r"(r2), "=r"(r3) : "r"(addr))

#define MMA16816(d, a, b) \
    asm volatile("mma.sync.aligned.m16n8k16.row.col.f32.f16.f16.f32 " \
                 "{%0,%1,%2,%3}, {%4,%5,%6,%7}, {%8,%9}, {%0,%1,%2,%3};" \
                 : "+f"((d)[0]), "+f"((d)[1]), "+f"((d)[2]), "+f"((d)[3]) \
                 : "r"((a)[0]), "r"((a)[1]), "r"((a)[2]), "r"((a)[3]), \
                   "r"((b)[0]), "r"((b)[1]))

// ================= precompute kernels ======================================
__global__ void prep_affine(const float* __restrict__ b1, const float* __restrict__ g1,
                            const float* __restrict__ be1, const float* __restrict__ m1,
                            const float* __restrict__ v1,
                            const float* __restrict__ b2, const float* __restrict__ g2,
                            const float* __restrict__ be2, const float* __restrict__ m2,
                            const float* __restrict__ v2)
{
    int i = threadIdx.x;
    if (i < 64) {
        float a = g1[i] * rsqrtf(v1[i] + 1e-5f);
        g_a1[i] = a;
        g_b1[i] = (b1[i] - m1[i]) * a + be1[i];
    }
    if (i < 96) {
        float a = g2[i] * rsqrtf(v2[i] + 1e-5f);
        g_a2[i] = a;
        g_b2[i] = (b2[i] - m2[i]) * a + be2[i];
    }
}

__global__ void cvt_coef_kernel(const float* __restrict__ c)
{
    int i = blockIdx.x * 256 + threadIdx.x;   // 512 x 256 = 131072
    g_Bh[i] = __float2half(c[i]);
}

// conv weights OIHW fp32 -> [k][oc][ic] fp16
__global__ void cvt_w_kernel(const float* __restrict__ w1, const float* __restrict__ w2)
{
    int i = blockIdx.x * 256 + threadIdx.x;   // 216 x 256 >= 55296
    if (i < 64 * 64 * 9) {
        int oc = i / 576, rem = i % 576, ic = rem / 9, k = rem % 9;
        g_W1h[(k * 64 + oc) * 64 + ic] = __float2half(w1[i]);
    }
    if (i < 96 * 64 * 9) {
        int oc = i / 576, rem = i % 576, ic = rem / 9, k = rem % 9;
        g_W2h[(k * 96 + oc) * 64 + ic] = __float2half(w2[i]);
    }
}

// ================= HMMA implicit-GEMM conv3x3 + BN + tanh ==================
template <int OC>
__global__ __launch_bounds__(256)
void conv_hmma_kernel(const float* __restrict__ xin, const __half* __restrict__ Wh,
                      const float* __restrict__ aff_a, const float* __restrict__ aff_b,
                      float* __restrict__ out)
{
    constexpr int NPW = OC / 2;
    constexpr int NPJ = NPW / 16;
    constexpr int NNI = NPW / 8;
    constexpr int XS_HALFS = 4 * 66 * 72;

    extern __shared__ __align__(16) char conv_sm[];
    __half* xs = (__half*)conv_sm;                    // [4][66][72]
    __half* Bs = (__half*)conv_sm + XS_HALFS;         // [2][OC][72]

    const int tid  = threadIdx.x;
    const int wid  = tid >> 5;
    const int lane = tid & 31;
    const int warp_m = wid & 3;
    const int warp_n = wid >> 2;
    const int h0 = blockIdx.x * 2;
    const int n  = blockIdx.y;

    auto wload = [&](int k, int buf) {
#pragma unroll
        for (int i = tid; i < OC * 8; i += 256) {
            int oc = i >> 3, c = i & 7;
            uint32_t dst = smem_u32(&Bs[(buf * OC + oc) * 72 + c * 8]);
            CP_ASYNC16(dst, Wh + ((size_t)k * OC + oc) * 64 + c * 8);
        }
        CP_ASYNC_COMMIT();
    };
    wload(0, 0);

    for (int idx = tid; idx < 4 * 64 * 66; idx += 256) {
        int w66 = idx % 66;
        int rest = idx / 66;
        int ic = rest & 63;
        int h4 = rest >> 6;
        int h = h0 - 1 + h4, w = w66 - 1;
        float v = 0.f;
        if (h >= 0 && h < 64 && w >= 0 && w < 64)
            v = xin[((n * 64 + ic) * 64 + h) * 64 + w];
        xs[(h4 * 66 + w66) * 72 + ic] = __float2half(v);
    }

    const int a_row  = lane & 15;
    const int a_colL = (lane >> 4) * 8;
    const int b_rowL = ((lane >> 4) * 8) + (lane & 7);
    const int b_colL = ((lane >> 3) & 1) * 8;

    int arow_lin[2];
#pragma unroll
    for (int mi = 0; mi < 2; mi++) {
        int m = warp_m * 32 + mi * 16 + a_row;
        arow_lin[mi] = (m >> 6) * 66 + (m & 63);
    }
    const uint32_t xbase = smem_u32(xs);

    float acc[2][NNI][4];
#pragma unroll
    for (int mi = 0; mi < 2; mi++)
#pragma unroll
        for (int ni = 0; ni < NNI; ni++)
#pragma unroll
            for (int q = 0; q < 4; q++) acc[mi][ni][q] = 0.f;

    for (int k = 0; k < 9; k++) {
        const int buf = k & 1;
        CP_ASYNC_WAIT(0);
        __syncthreads();
        if (k + 1 < 9) wload(k + 1, buf ^ 1);

        const int dh = k / 3, dw = k % 3;
        const uint32_t shift_off = (uint32_t)((dh * 66 + dw) * 72) * 2u;
        uint32_t arow_addr[2];
#pragma unroll
        for (int mi = 0; mi < 2; mi++)
            arow_addr[mi] = xbase + (uint32_t)(arow_lin[mi] * 72) * 2u + shift_off;
        const uint32_t bbase = smem_u32(&Bs[buf * OC * 72]);

#pragma unroll
        for (int kk = 0; kk < 4; kk++) {
            uint32_t a[2][4];
#pragma unroll
            for (int mi = 0; mi < 2; mi++)
                LDMATRIX_X4(a[mi][0], a[mi][1], a[mi][2], a[mi][3],
                            arow_addr[mi] + (uint32_t)(kk * 16 + a_colL) * 2u);
            uint32_t b[NPJ][4];
#pragma unroll
            for (int pj = 0; pj < NPJ; pj++) {
                int row = warp_n * NPW + pj * 16 + b_rowL;
                LDMATRIX_X4(b[pj][0], b[pj][1], b[pj][2], b[pj][3],
                            bbase + (uint32_t)(row * 72 + kk * 16 + b_colL) * 2u);
            }
#pragma unroll
            for (int mi = 0; mi < 2; mi++) {
#pragma unroll
                for (int ni = 0; ni < NNI; ni++) {
                    uint32_t bf[2];
                    bf[0] = b[ni >> 1][(ni & 1) * 2 + 0];
                    bf[1] = b[ni >> 1][(ni & 1) * 2 + 1];
                    MMA16816(acc[mi][ni], a[mi], bf);
                }
            }
        }
        __syncthreads();
    }

    const int lr = lane >> 2;
    const int lc = (lane & 3) * 2;
#pragma unroll
    for (int mi = 0; mi < 2; mi++) {
        int mbase = warp_m * 32 + mi * 16;
#pragma unroll
        for (int ni = 0; ni < NNI; ni++) {
            int oc0 = warp_n * NPW + ni * 8 + lc;
            float a0 = __ldg(&aff_a[oc0]),     c0 = __ldg(&aff_b[oc0]);
            float a1 = __ldg(&aff_a[oc0 + 1]), c1 = __ldg(&aff_b[oc0 + 1]);
#pragma unroll
            for (int hf = 0; hf < 2; hf++) {
                int m = mbase + lr + hf * 8;
                int h = h0 + (m >> 6), w = m & 63;
                out[((n * OC + oc0)     * 64 + h) * 64 + w] = tanhf(acc[mi][ni][hf * 2 + 0] * a0 + c0);
                out[((n * OC + oc0 + 1) * 64 + h) * 64 + w] = tanhf(acc[mi][ni][hf * 2 + 1] * a1 + c1);
            }
        }
    }
}

// ================= FUSED atoms + GEMM ======================================
// Block = 128 pixels (p0..p0+127: 2 w x 64 h, one n), all 128 outputs.
// Phase 1: stage x patch (64c x 66h x 4w fp32) + bases; Phase 2: atoms_s[m][k][f]
// (bc reads now h-CONTIGUOUS -> coalesced); Phase 3: K-chunk loop (16 x 64):
// produce As chunk in smem (thread = pixel x channel-pair; identical fp order
// to the passing R12 vals loop), cp.async B chunk, then the proven HMMA stage.
// g_Ah round-trip (268 MB DRAM) eliminated.
#define FS_XS    0
#define FS_ATOMS 67584
#define FS_AS    143360
#define FS_BS    180224
#define FS_BAS   217088
#define FS_TOTAL 217344

__global__ __launch_bounds__(256, 1)
void fused_atoms_gemm_kernel(const float* __restrict__ x, const float* __restrict__ bc,
                             const float* __restrict__ bases, const __half* __restrict__ B,
                             float* __restrict__ out)
{
    extern __shared__ __align__(16) char fsm[];
    float*  xs      = (float*)(fsm + FS_XS);      // [c(64)][hh(66)][ww(4)]
    float*  atoms_s = (float*)(fsm + FS_ATOMS);   // [m(128)][pad 148: k*16+f]
    __half* As      = (__half*)(fsm + FS_AS);     // [2][128][72]
    __half* Bs      = (__half*)(fsm + FS_BS);     // [2][128][72]
    float*  bs      = (float*)(fsm + FS_BAS);     // [54]

    const int tid  = threadIdx.x;
    const int wid  = tid >> 5;
    const int lane = tid & 31;
    const int bx   = blockIdx.x;
    const int n    = bx >> 5;
    const int wpair = (bx & 31) * 2;
    const int p0   = bx * 128;

    if (tid < 54) bs[tid] = bases[tid];

    // stage x patch: channels 0..63, gh -1..64, gw wpair-1..wpair+2
    for (int idx = tid; idx < 64 * 66 * 4; idx += 256) {
        int ww = idx & 3;
        int r  = idx >> 2;
        int hh = r % 66;
        int c  = r / 66;
        int gh = hh - 1, gw = wpair - 1 + ww;
        float v = 0.f;
        if (gh >= 0 && gh < 64 && gw >= 0 && gw < 64)
            v = x[((n * 64 + c) * 64 + gh) * 64 + gw];
        xs[idx] = v;
    }
    __syncthreads();

    // atoms_s: per (m,f), cv loads are h-contiguous across lanes (coalesced)
#pragma unroll 1
    for (int pr = 0; pr < 8; pr++) {
        int pair = tid + pr * 256;          // 0..2047
        int m = pair & 127;
        int f = pair >> 7;                  // 0..15
        int wq = wpair + (m >> 6);
        int hq = m & 63;
        float cv[6];
#pragma unroll
        for (int t = 0; t < 6; t++)
            cv[t] = __ldg(&bc[((n * 96 + f * 6 + t) * 64 + wq) * 64 + hq]);
#pragma unroll
        for (int k = 0; k < 9; k++) {
            float s = 0.f;
#pragma unroll
            for (int t = 0; t < 6; t++) s += cv[t] * bs[t * 9 + k];
            atoms_s[m * 148 + k * 16 + f] = s;
        }
    }

    auto bload = [&](int ks, int buf) {
#pragma unroll
        for (int i = tid; i < 1024; i += 256) {
            int o = i >> 3, cv8 = i & 7;
            CP_ASYNC16(smem_u32(&Bs[(buf * 128 + o) * 72 + cv8 * 8]),
                       B + (size_t)o * 1024 + ks * 64 + cv8 * 8);
        }
        CP_ASYNC_COMMIT();
    };
    __syncthreads();           // atoms_s ready for all
    bload(0, 0);

    const int warp_m = wid & 1;
    const int warp_n = wid >> 1;
    const int a_row_l = (lane & 15);
    const int a_col_l = (lane >> 4) * 8;
    const int b_row_l = ((lane >> 4) * 8) + (lane & 7);
    const int b_col_l = ((lane >> 3) & 1) * 8;

    const int mm    = tid >> 1;         // production pixel 0..127
    const int cpair = tid & 1;
    const int pw = mm >> 6, ph = mm & 63;
    const float* ap = &atoms_s[mm * 148];

    float acc[4][4][4];
#pragma unroll
    for (int mi = 0; mi < 4; mi++)
#pragma unroll
        for (int ni = 0; ni < 4; ni++)
#pragma unroll
            for (int q = 0; q < 4; q++) acc[mi][ni][q] = 0.f;

    for (int ks = 0; ks < 16; ks++) {
        const int buf = ks & 1;

        // ---- produce As[buf]: channels ks*4 + cpair*2 + {0,1} ----
#pragma unroll
        for (int cc = 0; cc < 2; cc++) {
            int c = ks * 4 + cpair * 2 + cc;
            float xr[9];
#pragma unroll
            for (int kh = 0; kh < 3; kh++)
#pragma unroll
                for (int kw = 0; kw < 3; kw++)
                    xr[kh * 3 + kw] = xs[(c * 66 + ph + kh) * 4 + pw + kw];

            const float4* ap4 = (const float4*)ap;
            float vals[16];
#pragma unroll
            for (int q = 0; q < 16; q++) vals[q] = 0.f;
#pragma unroll
            for (int k = 0; k < 9; k++) {
                float xk = xr[k];
                float4 q0 = ap4[k * 4 + 0];
                float4 q1 = ap4[k * 4 + 1];
                float4 q2 = ap4[k * 4 + 2];
                float4 q3 = ap4[k * 4 + 3];
                vals[0]  += xk * q0.x;  vals[1]  += xk * q0.y;
                vals[2]  += xk * q0.z;  vals[3]  += xk * q0.w;
                vals[4]  += xk * q1.x;  vals[5]  += xk * q1.y;
                vals[6]  += xk * q1.z;  vals[7]  += xk * q1.w;
                vals[8]  += xk * q2.x;  vals[9]  += xk * q2.y;
                vals[10] += xk * q2.z;  vals[11] += xk * q2.w;
                vals[12] += xk * q3.x;  vals[13] += xk * q3.y;
                vals[14] += xk * q3.z;  vals[15] += xk * q3.w;
            }
            union { __half2 h2[4]; uint4 u; } pk0, pk1;
#pragma unroll
            for (int q = 0; q < 4; q++) {
                pk0.h2[q] = __floats2half2_rn(vals[2 * q],     vals[2 * q + 1]);
                pk1.h2[q] = __floats2half2_rn(vals[8 + 2 * q], vals[8 + 2 * q + 1]);
            }
            uint4* dst = (uint4*)&As[(buf * 128 + mm) * 72 + (cpair * 2 + cc) * 16];
            dst[0] = pk0.u;
            dst[1] = pk1.u;
        }

        __syncthreads();    // As[buf] complete; all MMA(ks-1) done -> Bs[buf^1] free
        if (ks + 1 < 16) {
            bload(ks + 1, buf ^ 1);
            CP_ASYNC_WAIT(1);        // Bs[buf] ready
        } else {
            CP_ASYNC_WAIT(0);
        }

        // ---- MMA on chunk (4 x k16) ----
        const uint32_t aB = smem_u32(&As[buf * 128 * 72]);
        const uint32_t bB = smem_u32(&Bs[buf * 128 * 72]);
#pragma unroll
        for (int kk = 0; kk < 4; kk++) {
            uint32_t a[4][4];
#pragma unroll
            for (int mi = 0; mi < 4; mi++) {
                int row = warp_m * 64 + mi * 16 + a_row_l;
                int col = kk * 16 + a_col_l;
                LDMATRIX_X4(a[mi][0], a[mi][1], a[mi][2], a[mi][3],
                            aB + (uint32_t)(row * 72 + col) * 2);
            }
            uint32_t b[2][4];
#pragma unroll
            for (int pj = 0; pj < 2; pj++) {
                int row = warp_n * 32 + pj * 16 + b_row_l;
                int col = kk * 16 + b_col_l;
                LDMATRIX_X4(b[pj][0], b[pj][1], b[pj][2], b[pj][3],
                            bB + (uint32_t)(row * 72 + col) * 2);
            }
#pragma unroll
            for (int mi = 0; mi < 4; mi++) {
#pragma unroll
                for (int ni = 0; ni < 4; ni++) {
                    uint32_t bf[2];
                    bf[0] = b[ni >> 1][(ni & 1) * 2 + 0];
                    bf[1] = b[ni >> 1][(ni & 1) * 2 + 1];
                    MMA16816(acc[mi][ni], a[mi], bf);
                }
            }
        }
        __syncthreads();    // all MMA(ks) done before As[buf] rewritten at ks+2
    }

    // epilogue (identical to proven gemm): p = (n*64+w)*64+h ; out[n][o][w][h]
    const int lr = lane >> 2;
    const int lc = (lane & 3) * 2;
#pragma unroll
    for (int mi = 0; mi < 4; mi++) {
#pragma unroll
        for (int ni = 0; ni < 4; ni++) {
            int obase = warp_n * 32 + ni * 8 + lc;
#pragma unroll
            for (int half_ = 0; half_ < 2; half_++) {
                int p = p0 + warp_m * 64 + mi * 16 + lr + half_ * 8;
                int nn = p >> 12, wq = (p >> 6) & 63, hh = p & 63;
                size_t base = (((size_t)nn * 128) * 64 + (size_t)wq) * 64 + hh;
                out[base + (size_t)obase       * 4096] = acc[mi][ni][half_ * 2 + 0];
                out[base + (size_t)(obase + 1) * 4096] = acc[mi][ni][half_ * 2 + 1];
            }
        }
    }
}

// ================= launch ===================================================
extern "C" void kernel_launch(void* const* d_in, const int* in_sizes, int n_in,
                              void* d_out, int out_size)
{
    const float* x        = (const float*)d_in[0];
    const float* conv1_w  = (const float*)d_in[1];
    const float* conv1_b  = (const float*)d_in[2];
    const float* bn1_g    = (const float*)d_in[3];
    const float* bn1_be   = (const float*)d_in[4];
    const float* bn1_m    = (const float*)d_in[5];
    const float* bn1_v    = (const float*)d_in[6];
    const float* conv2_w  = (const float*)d_in[7];
    const float* conv2_b  = (const float*)d_in[8];
    const float* bn2_g    = (const float*)d_in[9];
    const float* bn2_be   = (const float*)d_in[10];
    const float* bn2_m    = (const float*)d_in[11];
    const float* bn2_v    = (const float*)d_in[12];
    const float* bases    = (const float*)d_in[13];
    const float* coef     = (const float*)d_in[14];
    float* out = (float*)d_out;

    static float  *p_h = nullptr, *p_bc = nullptr;
    static __half *p_Bh = nullptr, *p_W1h = nullptr, *p_W2h = nullptr;
    static float  *p_a1 = nullptr, *p_b1 = nullptr, *p_a2 = nullptr, *p_b2 = nullptr;
    if (!p_h) {
        cudaGetSymbolAddress((void**)&p_h,   g_h);
        cudaGetSymbolAddress((void**)&p_bc,  g_bc);
        cudaGetSymbolAddress((void**)&p_Bh,  g_Bh);
        cudaGetSymbolAddress((void**)&p_W1h, g_W1h);
        cudaGetSymbolAddress((void**)&p_W2h, g_W2h);
        cudaGetSymbolAddress((void**)&p_a1,  g_a1);
        cudaGetSymbolAddress((void**)&p_b1,  g_b1);
        cudaGetSymbolAddress((void**)&p_a2,  g_a2);
        cudaGetSymbolAddress((void**)&p_b2,  g_b2);
        cudaFuncSetAttribute(conv_hmma_kernel<64>, cudaFuncAttributeMaxDynamicSharedMemorySize,
                             (4 * 66 * 72 + 2 * 64 * 72) * 2);
        cudaFuncSetAttribute(conv_hmma_kernel<96>, cudaFuncAttributeMaxDynamicSharedMemorySize,
                             (4 * 66 * 72 + 2 * 96 * 72) * 2);
        cudaFuncSetAttribute(fused_atoms_gemm_kernel, cudaFuncAttributeMaxDynamicSharedMemorySize,
                             FS_TOTAL);
    }

    prep_affine<<<1, 128>>>(conv1_b, bn1_g, bn1_be, bn1_m, bn1_v,
                            conv2_b, bn2_g, bn2_be, bn2_m, bn2_v);
    cvt_coef_kernel<<<512, 256>>>(coef);
    cvt_w_kernel<<<216, 256>>>(conv1_w, conv2_w);

    conv_hmma_kernel<64><<<dim3(32, 16), 256, (4 * 66 * 72 + 2 * 64 * 72) * 2>>>(
        x, p_W1h, p_a1, p_b1, p_h);
    conv_hmma_kernel<96><<<dim3(32, 16), 256, (4 * 66 * 72 + 2 * 96 * 72) * 2>>>(
        p_h, p_W2h, p_a2, p_b2, p_bc);

    fused_atoms_gemm_kernel<<<512, 256, FS_TOTAL>>>(x, p_bc, bases, p_Bh, out);
}